// round 15
// baseline (speedup 1.0000x reference)
#include <cuda_runtime.h>
#include <float.h>

// Problem constants
#define B_   4
#define C_   64
#define T_   32
#define WH_  4096                  // W*H per frame
#define FRAME4_ (WH_ / 4)          // 1024 float4 per frame
#define FRAME8_ (WH_ / 8)          // 512 32B-units per frame
#define PLANE4_ ((T_ * WH_) / 4)   // 32768 float4 per (b,c) plane
#define PLANE8_ ((T_ * WH_) / 8)   // 16384 32B-units per (b,c) plane
#define NBT_ (B_ * T_)             // 128 frames

#define K1_CHUNKS  2               // blocks per frame in pass 1
#define K1_THREADS 256             // threads per block, one 32B unit each

// Scratch (device globals — no allocation)
__device__ float g_e[(size_t)NBT_ * WH_];          // unnormalized exp(fusion), 2MB
__device__ float g_part[NBT_ * K1_CHUNKS];         // per-chunk exp-sums

__device__ __forceinline__ float sigmoidf_(float v) {
    return 1.0f / (1.0f + __expf(-v));
}

// 32-byte global load (8 floats) with L2 evict-last priority.
// ptxas requires .v4.b64 (256-bit) for the L2::evict_last modifier.
__device__ __forceinline__ void ldg_evict_last_32B(
    const float* p, float4& a, float4& b)
{
    unsigned long long r0, r1, r2, r3;
    asm("ld.global.L2::evict_last.v4.b64 {%0,%1,%2,%3}, [%4];"
        : "=l"(r0), "=l"(r1), "=l"(r2), "=l"(r3) : "l"(p));
    a.x = __uint_as_float((unsigned)r0); a.y = __uint_as_float((unsigned)(r0 >> 32));
    a.z = __uint_as_float((unsigned)r1); a.w = __uint_as_float((unsigned)(r1 >> 32));
    b.x = __uint_as_float((unsigned)r2); b.y = __uint_as_float((unsigned)(r2 >> 32));
    b.z = __uint_as_float((unsigned)r3); b.w = __uint_as_float((unsigned)(r3 >> 32));
}

// ---------------- Pass 1: channel reduce + exp, partial sums ----------------
// grid (2, 128) = 256 blocks, 256 threads. One 32B unit per thread per channel:
// each channel iteration reads 8KB CONTIGUOUS per block; 2x bytes-in-flight per
// warp compensates the lower warp count. evict_last pins x in L2 for pass 2.
__global__ __launch_bounds__(K1_THREADS) void reduce_exp_kernel(
    const float* __restrict__ x,
    const float* __restrict__ skin)
{
    const int chunk = blockIdx.x;              // 0..1
    const int bt    = blockIdx.y;              // 0..127
    const int b     = bt >> 5;
    const int t     = bt & 31;
    const int tid   = threadIdx.x;             // 0..255
    const int p8    = chunk * K1_THREADS + tid;      // 0..511 (32B units in frame)

    const size_t base8 = ((size_t)(b * C_ * T_) + t) * FRAME8_ + p8;

    float4 s0 = make_float4(0.f, 0.f, 0.f, 0.f), s1 = s0;
    float4 m0 = make_float4(-FLT_MAX, -FLT_MAX, -FLT_MAX, -FLT_MAX), m1 = m0;

    #pragma unroll 8
    for (int c = 0; c < C_; c++) {
        float4 v0, v1;
        ldg_evict_last_32B(x + (base8 + (size_t)c * PLANE8_) * 8, v0, v1);
        s0.x += v0.x; s0.y += v0.y; s0.z += v0.z; s0.w += v0.w;
        m0.x = fmaxf(m0.x, v0.x); m0.y = fmaxf(m0.y, v0.y);
        m0.z = fmaxf(m0.z, v0.z); m0.w = fmaxf(m0.w, v0.w);
        s1.x += v1.x; s1.y += v1.y; s1.z += v1.z; s1.w += v1.w;
        m1.x = fmaxf(m1.x, v1.x); m1.y = fmaxf(m1.y, v1.y);
        m1.z = fmaxf(m1.z, v1.z); m1.w = fmaxf(m1.w, v1.w);
    }

    const size_t f4 = (size_t)bt * FRAME4_ + 2 * p8;   // float4 index of this unit
    const float4 k0 = __ldcs(&((const float4*)skin)[f4]);
    const float4 k1 = __ldcs(&((const float4*)skin)[f4 + 1]);

    const float inv_c = 1.0f / (float)C_;
    float4 e0, e1;
    // fusion in (0,3): exp is safe without max subtraction
    e0.x = __expf(sigmoidf_(s0.x * inv_c) + sigmoidf_(m0.x) + k0.x);
    e0.y = __expf(sigmoidf_(s0.y * inv_c) + sigmoidf_(m0.y) + k0.y);
    e0.z = __expf(sigmoidf_(s0.z * inv_c) + sigmoidf_(m0.z) + k0.z);
    e0.w = __expf(sigmoidf_(s0.w * inv_c) + sigmoidf_(m0.w) + k0.w);
    e1.x = __expf(sigmoidf_(s1.x * inv_c) + sigmoidf_(m1.x) + k1.x);
    e1.y = __expf(sigmoidf_(s1.y * inv_c) + sigmoidf_(m1.y) + k1.y);
    e1.z = __expf(sigmoidf_(s1.z * inv_c) + sigmoidf_(m1.z) + k1.z);
    e1.w = __expf(sigmoidf_(s1.w * inv_c) + sigmoidf_(m1.w) + k1.w);

    ((float4*)g_e)[f4]     = e0;
    ((float4*)g_e)[f4 + 1] = e1;

    // block sum of e (256 threads = 8 warps)
    float ls = (e0.x + e0.y + e0.z + e0.w) + (e1.x + e1.y + e1.z + e1.w);
    #pragma unroll
    for (int o = 16; o; o >>= 1) ls += __shfl_xor_sync(0xffffffffu, ls, o);

    __shared__ float red[8];
    if ((tid & 31) == 0) red[tid >> 5] = ls;
    __syncthreads();
    if (tid == 0) {
        float v = red[0];
        #pragma unroll
        for (int w = 1; w < 8; w++) v += red[w];
        g_part[bt * K1_CHUNKS + chunk] = v;
    }
}

// ---------------- Pass 2: out = x * e * inv_sum; c==0 planes write attn -------
// Reversed traversal to match pass-1 recency; __ldcs reads (demote the
// evict_last-pinned x lines after their single re-use), __stcs stores.
__global__ __launch_bounds__(256) void apply_kernel(
    const float* __restrict__ x,
    float* __restrict__ out,
    float* __restrict__ attn)
{
    const int plane = (B_ * C_ - 1) - blockIdx.y;        // 255..0
    const int blk   = (gridDim.x - 1) - blockIdx.x;      // 63..0
    const int b     = plane >> 6;
    const int c     = plane & 63;
    const int i4    = blk * 512 + threadIdx.x;           // first float4 index
    const int t     = blk >> 1;                           // block-constant frame
    const int bt    = b * T_ + t;

    const size_t px = (size_t)plane * PLANE4_ + i4;
    const size_t pa = (size_t)b * PLANE4_ + i4;   // index into g_e / attn

    const float4 xv0 = __ldcs(&((const float4*)x)[px]);
    const float4 xv1 = __ldcs(&((const float4*)x)[px + 256]);
    const float4 ev0 = __ldcs(&((const float4*)g_e)[pa]);
    const float4 ev1 = __ldcs(&((const float4*)g_e)[pa + 256]);

    const float* __restrict__ p = &g_part[bt * K1_CHUNKS];
    float tot = 0.f;
    #pragma unroll
    for (int r = 0; r < K1_CHUNKS; r++) tot += p[r];
    const float inv = __frcp_rn(tot);

    float4 a0, a1;
    a0.x = ev0.x * inv; a0.y = ev0.y * inv; a0.z = ev0.z * inv; a0.w = ev0.w * inv;
    a1.x = ev1.x * inv; a1.y = ev1.y * inv; a1.z = ev1.z * inv; a1.w = ev1.w * inv;

    float4 o0, o1;
    o0.x = xv0.x * a0.x; o0.y = xv0.y * a0.y; o0.z = xv0.z * a0.z; o0.w = xv0.w * a0.w;
    o1.x = xv1.x * a1.x; o1.y = xv1.y * a1.y; o1.z = xv1.z * a1.z; o1.w = xv1.w * a1.w;

    __stcs(&((float4*)out)[px],       o0);
    __stcs(&((float4*)out)[px + 256], o1);

    if (c == 0) {
        __stcs(&((float4*)attn)[pa],       a0);
        __stcs(&((float4*)attn)[pa + 256], a1);
    }
}

extern "C" void kernel_launch(void* const* d_in, const int* in_sizes, int n_in,
                              void* d_out, int out_size)
{
    const float* x    = (const float*)d_in[0];
    const float* skin = (const float*)d_in[1];
    float* out  = (float*)d_out;
    float* attn = out + (size_t)B_ * C_ * T_ * WH_;   // second output region

    dim3 g1(K1_CHUNKS, NBT_);
    reduce_exp_kernel<<<g1, K1_THREADS>>>(x, skin);

    dim3 g2(PLANE4_ / 512, B_ * C_);
    apply_kernel<<<g2, 256>>>(x, out, attn);
}

// round 16
// speedup vs baseline: 1.1285x; 1.1285x over previous
#include <cuda_runtime.h>
#include <float.h>

// Problem constants
#define B_   4
#define C_   64
#define T_   32
#define WH_  4096                  // W*H per frame
#define FRAME4_ (WH_ / 4)          // 1024 float4 per frame
#define PLANE4_ ((T_ * WH_) / 4)   // 32768 float4 per (b,c) plane
#define NBT_ (B_ * T_)             // 128 frames

#define K1_CHUNKS  4               // blocks per frame in pass 1
#define K1_THREADS 256             // threads per block (1 float4 each)

// Scratch (device globals — no allocation)
__device__ float g_e[(size_t)NBT_ * WH_];          // unnormalized exp(fusion), 2MB
__device__ float g_part[NBT_ * K1_CHUNKS];         // per-chunk exp-sums

__device__ __forceinline__ float sigmoidf_(float v) {
    return 1.0f / (1.0f + __expf(-v));
}

#define ACC(v) \
    s.x += (v).x; s.y += (v).y; s.z += (v).z; s.w += (v).w; \
    m.x = fmaxf(m.x, (v).x); m.y = fmaxf(m.y, (v).y);       \
    m.z = fmaxf(m.z, (v).z); m.w = fmaxf(m.w, (v).w);

// ---------------- Pass 1: channel reduce + exp, partial sums ----------------
// grid (4, 128) = 512 blocks, 256 threads, 1 float4/thread.
// The c-loop loads 8 float4 into EXPLICIT live registers before any use so
// ptxas front-batches 8 LDG.128 (MLP=8). __launch_bounds__(256,4) permits
// 64 regs (vs the 32 ptxas chose before, which limited MLP to ~2-3) while
// keeping 32 warps/SM — past the measured occupancy saturation point.
__global__ __launch_bounds__(K1_THREADS, 4) void reduce_exp_kernel(
    const float* __restrict__ x,
    const float* __restrict__ skin)
{
    const int chunk = blockIdx.x;              // 0..3
    const int bt    = blockIdx.y;              // 0..127
    const int b     = bt >> 5;
    const int t     = bt & 31;
    const int tid   = threadIdx.x;
    const int p4    = chunk * K1_THREADS + tid;      // 0..1023 within frame

    const size_t base4 = ((size_t)(b * C_ * T_) + t) * FRAME4_ + p4;
    const float4* __restrict__ x4 = (const float4*)x;

    float4 s = make_float4(0.f, 0.f, 0.f, 0.f);
    float4 m = make_float4(-FLT_MAX, -FLT_MAX, -FLT_MAX, -FLT_MAX);

    #pragma unroll 1
    for (int c = 0; c < C_; c += 8) {
        const float4* p = &x4[base4 + (size_t)c * PLANE4_];
        // 8 independent loads, all issued before first use:
        const float4 v0 = p[0 * PLANE4_];
        const float4 v1 = p[1 * PLANE4_];
        const float4 v2 = p[2 * PLANE4_];
        const float4 v3 = p[3 * PLANE4_];
        const float4 v4 = p[4 * PLANE4_];
        const float4 v5 = p[5 * PLANE4_];
        const float4 v6 = p[6 * PLANE4_];
        const float4 v7 = p[7 * PLANE4_];
        ACC(v0) ACC(v1) ACC(v2) ACC(v3)
        ACC(v4) ACC(v5) ACC(v6) ACC(v7)
    }

    const float4 k = __ldcs(&((const float4*)skin)[(size_t)bt * FRAME4_ + p4]);

    const float inv_c = 1.0f / (float)C_;
    float4 e;
    // fusion in (0,3): exp is safe without max subtraction
    e.x = __expf(sigmoidf_(s.x * inv_c) + sigmoidf_(m.x) + k.x);
    e.y = __expf(sigmoidf_(s.y * inv_c) + sigmoidf_(m.y) + k.y);
    e.z = __expf(sigmoidf_(s.z * inv_c) + sigmoidf_(m.z) + k.z);
    e.w = __expf(sigmoidf_(s.w * inv_c) + sigmoidf_(m.w) + k.w);

    ((float4*)g_e)[(size_t)bt * FRAME4_ + p4] = e;

    // block sum of e
    float ls = e.x + e.y + e.z + e.w;
    #pragma unroll
    for (int o = 16; o; o >>= 1) ls += __shfl_xor_sync(0xffffffffu, ls, o);

    __shared__ float red[8];
    if ((tid & 31) == 0) red[tid >> 5] = ls;
    __syncthreads();
    if (tid == 0) {
        float v = red[0];
        #pragma unroll
        for (int w = 1; w < 8; w++) v += red[w];
        g_part[bt * K1_CHUNKS + chunk] = v;
    }
}

// ---------------- Pass 2: out = x * e * inv_sum; c==0 planes write attn -------
// Exactly the R6 best-measured apply: reversed traversal, __ldcs loads,
// __stcs stores.
__global__ __launch_bounds__(256) void apply_kernel(
    const float* __restrict__ x,
    float* __restrict__ out,
    float* __restrict__ attn)
{
    const int plane = (B_ * C_ - 1) - blockIdx.y;        // 255..0
    const int blk   = (gridDim.x - 1) - blockIdx.x;      // 63..0
    const int b     = plane >> 6;
    const int c     = plane & 63;
    const int i4    = blk * 512 + threadIdx.x;           // first float4 index
    const int t     = blk >> 1;                           // block-constant frame
    const int bt    = b * T_ + t;

    const size_t px = (size_t)plane * PLANE4_ + i4;
    const size_t pa = (size_t)b * PLANE4_ + i4;   // index into g_e / attn

    const float4 xv0 = __ldcs(&((const float4*)x)[px]);
    const float4 xv1 = __ldcs(&((const float4*)x)[px + 256]);
    const float4 ev0 = __ldcs(&((const float4*)g_e)[pa]);
    const float4 ev1 = __ldcs(&((const float4*)g_e)[pa + 256]);

    const float* __restrict__ p = &g_part[bt * K1_CHUNKS];
    float tot = 0.f;
    #pragma unroll
    for (int r = 0; r < K1_CHUNKS; r++) tot += p[r];
    const float inv = __frcp_rn(tot);

    float4 a0, a1;
    a0.x = ev0.x * inv; a0.y = ev0.y * inv; a0.z = ev0.z * inv; a0.w = ev0.w * inv;
    a1.x = ev1.x * inv; a1.y = ev1.y * inv; a1.z = ev1.z * inv; a1.w = ev1.w * inv;

    float4 o0, o1;
    o0.x = xv0.x * a0.x; o0.y = xv0.y * a0.y; o0.z = xv0.z * a0.z; o0.w = xv0.w * a0.w;
    o1.x = xv1.x * a1.x; o1.y = xv1.y * a1.y; o1.z = xv1.z * a1.z; o1.w = xv1.w * a1.w;

    __stcs(&((float4*)out)[px],       o0);
    __stcs(&((float4*)out)[px + 256], o1);

    if (c == 0) {
        __stcs(&((float4*)attn)[pa],       a0);
        __stcs(&((float4*)attn)[pa + 256], a1);
    }
}

extern "C" void kernel_launch(void* const* d_in, const int* in_sizes, int n_in,
                              void* d_out, int out_size)
{
    const float* x    = (const float*)d_in[0];
    const float* skin = (const float*)d_in[1];
    float* out  = (float*)d_out;
    float* attn = out + (size_t)B_ * C_ * T_ * WH_;   // second output region

    dim3 g1(K1_CHUNKS, NBT_);
    reduce_exp_kernel<<<g1, K1_THREADS>>>(x, skin);

    dim3 g2(PLANE4_ / 512, B_ * C_);
    apply_kernel<<<g2, 256>>>(x, out, attn);
}